// round 10
// baseline (speedup 1.0000x reference)
#include <cuda_runtime.h>

// Problem constants (fixed shapes)
#define BB   2
#define NN   2048
#define DD   768
#define HH   12
#define DH   64
#define DP   192
#define NPOS 4095   // 2*N - 1

typedef unsigned long long u64;

// ---------------- f32x2 packed-math helpers (FFMA2 path, sm_103a) -------------
__device__ __forceinline__ u64 pk2(float lo, float hi) {
    u64 r; asm("mov.b64 %0, {%1, %2};" : "=l"(r) : "f"(lo), "f"(hi)); return r;
}
__device__ __forceinline__ float2 upk2(u64 v) {
    float2 r; asm("mov.b64 {%0, %1}, %2;" : "=f"(r.x), "=f"(r.y) : "l"(v)); return r;
}
__device__ __forceinline__ void fma2(u64 &d, u64 a, u64 b) {
    asm("fma.rn.f32x2 %0, %1, %2, %0;" : "+l"(d) : "l"(a), "l"(b));
}
__device__ __forceinline__ void mul2(u64 &d, u64 a) {
    asm("mul.rn.f32x2 %0, %0, %1;" : "+l"(d) : "l"(a));
}

// ---------------- cp.async helpers (LDGSTS) -----------------------------------
__device__ __forceinline__ void cpa16(void* smem_dst, const void* gmem_src) {
    unsigned s = (unsigned)__cvta_generic_to_shared(smem_dst);
    asm volatile("cp.async.cg.shared.global [%0], [%1], 16;" :: "r"(s), "l"(gmem_src));
}
__device__ __forceinline__ void cpa_commit() {
    asm volatile("cp.async.commit_group;");
}
__device__ __forceinline__ void cpa_wait0() {
    asm volatile("cp.async.wait_group 0;");
}

// ---------------- scratch (device globals; no allocations allowed) ------------
__device__ float g_q[(size_t)BB*HH*NN*DH];     // [b,h,n,d], pre-scaled by 1/8
__device__ float g_k[(size_t)BB*HH*NN*DH];
__device__ float g_v[(size_t)BB*HH*NN*DH];
__device__ float g_vals[(size_t)NPOS*HH];      // DPB MLP output [2N-1, H]
__device__ float g_o[(size_t)BB*NN*DD];        // attention output [b,n,h*64+d]
__device__ float g_xT[(size_t)DD*BB*NN];       // x transposed [768][4096]
__device__ float g_oT[(size_t)DD*BB*NN];       // g_o transposed [768][4096]

// =============================================================================
// Kernel 0: 32x32 tiled transpose  [4096,768] -> [768,4096]
// mode 0: src = x (param) -> g_xT ;  mode 1: src = g_o -> g_oT
// =============================================================================
__global__ void transpose_k(const float* __restrict__ src_p, int mode)
{
    __shared__ float t[32][33];
    const float* src = mode ? g_o : src_p;
    float* dst = mode ? g_oT : g_xT;
    const int x0 = blockIdx.x * 32;   // row index in src (0..4095)
    const int y0 = blockIdx.y * 32;   // col index in src (0..767)
    const int tx = threadIdx.x, ty = threadIdx.y;
#pragma unroll
    for (int j = 0; j < 32; j += 8)
        t[ty + j][tx] = src[(size_t)(x0 + ty + j) * DD + y0 + tx];
    __syncthreads();
#pragma unroll
    for (int j = 0; j < 32; j += 8)
        dst[(size_t)(y0 + ty + j) * (BB * NN) + x0 + tx] = t[tx][ty + j];
}

// =============================================================================
// Kernel 1: 128x128-tile SGEMM, f32x2 FMAs, BK=32, double-buffered, both
// operands staged via cp.async (A pre-transposed).  M-packed accumulators:
// A pairs load free as u64 from smem; only B is duplicated (8 movs / 32 FMA2).
// 256 threads, 8 rows x 8 cols per thread.
// mode 0: A = g_xT, B = qkv_w [768,2304], scatter q/k/v (+bias, q*0.125)
// mode 1: A = g_oT, B = out_w [768,768],  write outp (+bias)
// =============================================================================
__global__ __launch_bounds__(256, 2) void big_gemm(const float* __restrict__ Bm,
                                                   int ldb, int mode,
                                                   const float* __restrict__ bias,
                                                   float* __restrict__ outp)
{
    __shared__ float As[2][32][132];   // As[buf][k][m]
    __shared__ float Bs[2][32][132];   // Bs[buf][k][n]
    const float* AT = mode ? g_oT : g_xT;
    const int bm = blockIdx.y * 128;
    const int bn = blockIdx.x * 128;
    const int tid = threadIdx.x;
    const int tx = tid & 15, ty = tid >> 4;
    const int srow = tid >> 3;          // staging row 0..31
    const int sch  = (tid & 7) * 4;     // staging col group (floats)

    u64 acc[4][8];                      // [m-pair][col]
#pragma unroll
    for (int p = 0; p < 4; p++)
#pragma unroll
        for (int c = 0; c < 8; c++) acc[p][c] = 0ULL;

    auto stage = [&](int buf, int kt) {
        const int k0 = kt * 32;
        const float* Asrc = &AT[(size_t)(k0 + srow) * (BB * NN) + bm + sch];
        const float* Bsrc = &Bm[(size_t)(k0 + srow) * ldb + bn + sch];
        float* Adst = &As[buf][srow][sch];
        float* Bdst = &Bs[buf][srow][sch];
#pragma unroll
        for (int q = 0; q < 4; q++) {
            cpa16(Adst + q * 32, Asrc + q * 32);
            cpa16(Bdst + q * 32, Bsrc + q * 32);
        }
        cpa_commit();
    };

    stage(0, 0);

    for (int kt = 0; kt < 24; kt++) {
        const int cb = kt & 1, nb = cb ^ 1;
        cpa_wait0();
        __syncthreads();
        if (kt < 23) stage(nb, kt + 1);
#pragma unroll 8
        for (int kk = 0; kk < 32; kk++) {
            const u64* a64 = reinterpret_cast<const u64*>(&As[cb][kk][ty * 8]);
            u64 ap0 = a64[0], ap1 = a64[1], ap2 = a64[2], ap3 = a64[3];
            float4 b0 = *reinterpret_cast<const float4*>(&Bs[cb][kk][tx * 4]);
            float4 b1 = *reinterpret_cast<const float4*>(&Bs[cb][kk][64 + tx * 4]);
            u64 bd[8];
            bd[0] = pk2(b0.x, b0.x); bd[1] = pk2(b0.y, b0.y);
            bd[2] = pk2(b0.z, b0.z); bd[3] = pk2(b0.w, b0.w);
            bd[4] = pk2(b1.x, b1.x); bd[5] = pk2(b1.y, b1.y);
            bd[6] = pk2(b1.z, b1.z); bd[7] = pk2(b1.w, b1.w);
#pragma unroll
            for (int c = 0; c < 8; c++) {
                fma2(acc[0][c], ap0, bd[c]);
                fma2(acc[1][c], ap1, bd[c]);
                fma2(acc[2][c], ap2, bd[c]);
                fma2(acc[3][c], ap3, bd[c]);
            }
        }
    }

    // ---- epilogue: unpack m-pairs ----
#pragma unroll
    for (int g = 0; g < 2; g++) {
        const int col0 = bn + g * 64 + tx * 4;
        float4 bz = *reinterpret_cast<const float4*>(&bias[col0]);
        if (mode == 0) {
            const int t   = col0 / 768;           // 0=q, 1=k, 2=v
            const int rem = col0 - t * 768;
            const int h   = rem >> 6;
            const int d0  = rem & 63;
            float* dst = (t == 0) ? g_q : (t == 1) ? g_k : g_v;
            const float sc = (t == 0) ? 0.125f : 1.0f;
#pragma unroll
            for (int p = 0; p < 4; p++) {
                float2 c0 = upk2(acc[p][g * 4 + 0]);
                float2 c1 = upk2(acc[p][g * 4 + 1]);
                float2 c2 = upk2(acc[p][g * 4 + 2]);
                float2 c3 = upk2(acc[p][g * 4 + 3]);
#pragma unroll
                for (int dd = 0; dd < 2; dd++) {
                    int row = bm + ty * 8 + 2 * p + dd;
                    int b = row >> 11, n = row & 2047;
                    float4 o;
                    o.x = ((dd ? c0.y : c0.x) + bz.x) * sc;
                    o.y = ((dd ? c1.y : c1.x) + bz.y) * sc;
                    o.z = ((dd ? c2.y : c2.x) + bz.z) * sc;
                    o.w = ((dd ? c3.y : c3.x) + bz.w) * sc;
                    *reinterpret_cast<float4*>(
                        &dst[(((size_t)b * HH + h) * NN + n) * DH + d0]) = o;
                }
            }
        } else {
#pragma unroll
            for (int p = 0; p < 4; p++) {
                float2 c0 = upk2(acc[p][g * 4 + 0]);
                float2 c1 = upk2(acc[p][g * 4 + 1]);
                float2 c2 = upk2(acc[p][g * 4 + 2]);
                float2 c3 = upk2(acc[p][g * 4 + 3]);
#pragma unroll
                for (int dd = 0; dd < 2; dd++) {
                    int row = bm + ty * 8 + 2 * p + dd;
                    float4 o;
                    o.x = (dd ? c0.y : c0.x) + bz.x;
                    o.y = (dd ? c1.y : c1.x) + bz.y;
                    o.z = (dd ? c2.y : c2.x) + bz.z;
                    o.w = (dd ? c3.y : c3.x) + bz.w;
                    *reinterpret_cast<float4*>(&outp[(size_t)row * 768 + col0]) = o;
                }
            }
        }
    }
}

// =============================================================================
// Kernel 2: DynamicPositionBias MLP, fully fused.  16 rows per block, 192 thr.
// =============================================================================
__global__ __launch_bounds__(192) void dpb_kernel(const float* __restrict__ w_in,
                                                  const float* __restrict__ b_in,
                                                  const float* __restrict__ w_hid,
                                                  const float* __restrict__ b_hid,
                                                  const float* __restrict__ ln_g,
                                                  const float* __restrict__ ln_b,
                                                  const float* __restrict__ w_out,
                                                  const float* __restrict__ b_out)
{
    __shared__ float hbuf[16][DP];
    __shared__ float tmp[16][DP];
    __shared__ float mu_s[16], rs_s[16];
    const int j    = threadIdx.x;         // 0..191
    const int r0   = blockIdx.x * 16;
    const int warp = j >> 5, lane = j & 31;

    const float wi = w_in[j], bi = b_in[j];
#pragma unroll
    for (int r = 0; r < 16; r++) {
        float p = (float)(r0 + r) - 2047.0f;
        float sg = (p > 0.f) ? 1.f : ((p < 0.f) ? -1.f : 0.f);
        float pv = sg * logf(fabsf(p) + 1.f);
        tmp[r][j] = pv * wi + bi;
    }
    __syncthreads();

    for (int layer = 0; layer < 4; layer++) {
        for (int r = warp; r < 16; r += 6) {
            float s = 0.f, s2 = 0.f;
            for (int k = lane; k < DP; k += 32) {
                float v = tmp[r][k];
                s += v; s2 += v * v;
            }
#pragma unroll
            for (int off = 16; off > 0; off >>= 1) {
                s  += __shfl_xor_sync(0xffffffffu, s,  off);
                s2 += __shfl_xor_sync(0xffffffffu, s2, off);
            }
            if (lane == 0) {
                float mu = s * (1.0f / DP);
                float var = s2 * (1.0f / DP) - mu * mu;
                mu_s[r] = mu;
                rs_s[r] = rsqrtf(var + 1e-5f);
            }
        }
        __syncthreads();
        const float gj = ln_g[layer * DP + j], bj = ln_b[layer * DP + j];
#pragma unroll
        for (int r = 0; r < 16; r++) {
            float v = (tmp[r][j] - mu_s[r]) * rs_s[r] * gj + bj;
            hbuf[r][j] = v / (1.f + expf(-v));    // SiLU
        }
        __syncthreads();

        if (layer < 3) {
            float acc[16];
#pragma unroll
            for (int r = 0; r < 16; r++) acc[r] = 0.f;
            const float* Wp = w_hid + (size_t)layer * DP * DP + j;
            for (int k = 0; k < DP; k++) {
                float w = Wp[(size_t)k * DP];
#pragma unroll
                for (int r = 0; r < 16; r++) acc[r] = fmaf(hbuf[r][k], w, acc[r]);
            }
            const float bh = b_hid[layer * DP + j];
#pragma unroll
            for (int r = 0; r < 16; r++) tmp[r][j] = acc[r] + bh;
            __syncthreads();
        }
    }

    const int rr = j / 12, cc = j - rr * 12;
    float a = 0.f;
    for (int k = 0; k < DP; k++) a = fmaf(hbuf[rr][k], w_out[k * 12 + cc], a);
    const int row = r0 + rr;
    if (row < NPOS) g_vals[(size_t)row * HH + cc] = a + b_out[cc];
}

// =============================================================================
// Kernel 3: flash attention, 128 q x 64 k per tile, 256 threads, 2 CTAs/SM.
// M-packed f32x2 accumulators: Q/P pairs load free as u64; K/V duplicated
// (4 movs per 16 FMA2).
// =============================================================================
#define QS 132   // stride for 128-wide transposed tiles (Qs, Ps)
#define KS 68    // stride for 64-wide tiles (Ks, Vs)

__global__ __launch_bounds__(256, 2) void attn_kernel()
{
    extern __shared__ float sm[];
    float* Qs     = sm;                     // [64][132] transposed: Qs[d][m]
    float* Ps     = Qs + 64 * QS;           // [64][132] transposed: Ps[k][m]
    float* Ks     = Ps + 64 * QS;           // [64][68]  transposed: Ks[d][n]
    float* Vs     = Ks + 64 * KS;           // [64][68]  natural:    Vs[k][d]
    float* vals_s = Vs + 64 * KS;           // [192] bias diagonal slice

    const int bh = blockIdx.y;
    const int b  = bh / HH, h = bh - b * HH;
    const int q0 = blockIdx.x * 128;
    const float* Qg = g_q + (size_t)bh * NN * DH;
    const float* Kg = g_k + (size_t)bh * NN * DH;
    const float* Vg = g_v + (size_t)bh * NN * DH;

    const int tid = threadIdx.x;
    const int tx = tid & 15, ty = tid >> 4;
    const int sm_m  = tid >> 4;            // 0..15 base row for staging
    const int sm_c4 = (tid & 15) << 2;     // 0..60 col group for staging

    // ---- load Q tile (128x64) transposed; q already scaled by Dh^-0.5 ----
#pragma unroll
    for (int i = 0; i < 8; i++) {
        int m = sm_m + i * 16;
        float4 v = *reinterpret_cast<const float4*>(&Qg[(size_t)(q0 + m) * DH + sm_c4]);
        Qs[(sm_c4 + 0) * QS + m] = v.x;
        Qs[(sm_c4 + 1) * QS + m] = v.y;
        Qs[(sm_c4 + 2) * QS + m] = v.z;
        Qs[(sm_c4 + 3) * QS + m] = v.w;
    }

    float m_i[8], l_i[8];
    u64 oacc[4][4];   // [m-pair][col]
#pragma unroll
    for (int i = 0; i < 8; i++) { m_i[i] = -1e30f; l_i[i] = 0.f; }
#pragma unroll
    for (int p = 0; p < 4; p++)
#pragma unroll
        for (int j = 0; j < 4; j++) oacc[p][j] = 0ULL;

    for (int kt = 0; kt < NN / 64; kt++) {
        const int kk0 = kt * 64;
        // stage K (transposed via regs), V (cp.async), bias slice
#pragma unroll
        for (int i = 0; i < 4; i++) {
            int m = sm_m + i * 16;
            float4 kv = *reinterpret_cast<const float4*>(&Kg[(size_t)(kk0 + m) * DH + sm_c4]);
            cpa16(&Vs[m * KS + sm_c4], &Vg[(size_t)(kk0 + m) * DH + sm_c4]);
            Ks[(sm_c4 + 0) * KS + m] = kv.x;
            Ks[(sm_c4 + 1) * KS + m] = kv.y;
            Ks[(sm_c4 + 2) * KS + m] = kv.z;
            Ks[(sm_c4 + 3) * KS + m] = kv.w;
        }
        cpa_commit();
        if (tid < 191) vals_s[tid] = g_vals[(size_t)(q0 - kk0 + 2047 - 63 + tid) * HH + h];
        cpa_wait0();
        __syncthreads();

        // S = Q @ K^T  (128x64), M-packed f32x2 accumulation
        u64 sacc[4][4];
#pragma unroll
        for (int p = 0; p < 4; p++)
#pragma unroll
            for (int j = 0; j < 4; j++) sacc[p][j] = 0ULL;
#pragma unroll 4
        for (int d = 0; d < 64; d++) {
            const u64* q64 = reinterpret_cast<const u64*>(&Qs[d * QS + ty * 8]);
            u64 qp0 = q64[0], qp1 = q64[1], qp2 = q64[2], qp3 = q64[3];
            float4 kb = *reinterpret_cast<const float4*>(&Ks[d * KS + tx * 4]);
            u64 b0 = pk2(kb.x, kb.x), b1 = pk2(kb.y, kb.y);
            u64 b2 = pk2(kb.z, kb.z), b3 = pk2(kb.w, kb.w);
            fma2(sacc[0][0], qp0, b0); fma2(sacc[0][1], qp0, b1);
            fma2(sacc[0][2], qp0, b2); fma2(sacc[0][3], qp0, b3);
            fma2(sacc[1][0], qp1, b0); fma2(sacc[1][1], qp1, b1);
            fma2(sacc[1][2], qp1, b2); fma2(sacc[1][3], qp1, b3);
            fma2(sacc[2][0], qp2, b0); fma2(sacc[2][1], qp2, b1);
            fma2(sacc[2][2], qp2, b2); fma2(sacc[2][3], qp2, b3);
            fma2(sacc[3][0], qp3, b0); fma2(sacc[3][1], qp3, b1);
            fma2(sacc[3][2], qp3, b2); fma2(sacc[3][3], qp3, b3);
        }

        // + bias, online softmax (rows share 16 threads; shfl width 16)
        float alpha8[8];
#pragma unroll
        for (int p = 0; p < 4; p++) {
            float2 c0 = upk2(sacc[p][0]);
            float2 c1 = upk2(sacc[p][1]);
            float2 c2 = upk2(sacc[p][2]);
            float2 c3 = upk2(sacc[p][3]);
#pragma unroll
            for (int dd = 0; dd < 2; dd++) {
                const int i = 2 * p + dd;
                float s0 = dd ? c0.y : c0.x;
                float s1 = dd ? c1.y : c1.x;
                float s2 = dd ? c2.y : c2.x;
                float s3 = dd ? c3.y : c3.x;
                int moff = ty * 8 + i - tx * 4 + 63;
                s0 += vals_s[moff];
                s1 += vals_s[moff - 1];
                s2 += vals_s[moff - 2];
                s3 += vals_s[moff - 3];
                float rm = fmaxf(fmaxf(s0, s1), fmaxf(s2, s3));
#pragma unroll
                for (int off = 8; off > 0; off >>= 1)
                    rm = fmaxf(rm, __shfl_xor_sync(0xffffffffu, rm, off, 16));
                float mnew  = fmaxf(m_i[i], rm);
                float alpha = __expf(m_i[i] - mnew);
                s0 = __expf(s0 - mnew);
                s1 = __expf(s1 - mnew);
                s2 = __expf(s2 - mnew);
                s3 = __expf(s3 - mnew);
                float rsum = s0 + s1 + s2 + s3;
#pragma unroll
                for (int off = 8; off > 0; off >>= 1)
                    rsum += __shfl_xor_sync(0xffffffffu, rsum, off, 16);
                l_i[i] = l_i[i] * alpha + rsum;
                m_i[i] = mnew;
                alpha8[i] = alpha;
                // write P transposed for the PV GEMM
                Ps[(tx * 4 + 0) * QS + ty * 8 + i] = s0;
                Ps[(tx * 4 + 1) * QS + ty * 8 + i] = s1;
                Ps[(tx * 4 + 2) * QS + ty * 8 + i] = s2;
                Ps[(tx * 4 + 3) * QS + ty * 8 + i] = s3;
            }
        }
        // rescale O accumulators (packed alpha per m-pair)
#pragma unroll
        for (int p = 0; p < 4; p++) {
            u64 alp = pk2(alpha8[2 * p], alpha8[2 * p + 1]);
            mul2(oacc[p][0], alp);
            mul2(oacc[p][1], alp);
            mul2(oacc[p][2], alp);
            mul2(oacc[p][3], alp);
        }
        __syncthreads();   // Ps visible to all warps

        // O += P @ V  (128x64 += 128x64 @ 64x64), M-packed f32x2
#pragma unroll 4
        for (int k = 0; k < 64; k++) {
            const u64* p64 = reinterpret_cast<const u64*>(&Ps[k * QS + ty * 8]);
            u64 pp0 = p64[0], pp1 = p64[1], pp2 = p64[2], pp3 = p64[3];
            float4 vb = *reinterpret_cast<const float4*>(&Vs[k * KS + tx * 4]);
            u64 b0 = pk2(vb.x, vb.x), b1 = pk2(vb.y, vb.y);
            u64 b2 = pk2(vb.z, vb.z), b3 = pk2(vb.w, vb.w);
            fma2(oacc[0][0], pp0, b0); fma2(oacc[0][1], pp0, b1);
            fma2(oacc[0][2], pp0, b2); fma2(oacc[0][3], pp0, b3);
            fma2(oacc[1][0], pp1, b0); fma2(oacc[1][1], pp1, b1);
            fma2(oacc[1][2], pp1, b2); fma2(oacc[1][3], pp1, b3);
            fma2(oacc[2][0], pp2, b0); fma2(oacc[2][1], pp2, b1);
            fma2(oacc[2][2], pp2, b2); fma2(oacc[2][3], pp2, b3);
            fma2(oacc[3][0], pp3, b0); fma2(oacc[3][1], pp3, b1);
            fma2(oacc[3][2], pp3, b2); fma2(oacc[3][3], pp3, b3);
        }
        __syncthreads();   // done reading Ks/Vs/vals before next stage
    }

    // normalize and store to [b,n,h*64+d] for the output projection
#pragma unroll
    for (int p = 0; p < 4; p++) {
        float2 c0 = upk2(oacc[p][0]);
        float2 c1 = upk2(oacc[p][1]);
        float2 c2 = upk2(oacc[p][2]);
        float2 c3 = upk2(oacc[p][3]);
#pragma unroll
        for (int dd = 0; dd < 2; dd++) {
            const int i = 2 * p + dd;
            float inv = 1.0f / l_i[i];
            float4 o;
            o.x = (dd ? c0.y : c0.x) * inv;
            o.y = (dd ? c1.y : c1.x) * inv;
            o.z = (dd ? c2.y : c2.x) * inv;
            o.w = (dd ? c3.y : c3.x) * inv;
            size_t row = (size_t)b * NN + q0 + ty * 8 + i;
            *reinterpret_cast<float4*>(&g_o[row * DD + h * DH + tx * 4]) = o;
        }
    }
}

// =============================================================================
extern "C" void kernel_launch(void* const* d_in, const int* in_sizes, int n_in,
                              void* d_out, int out_size)
{
    const float* x         = (const float*)d_in[0];
    const float* qkv_w     = (const float*)d_in[1];
    const float* qkv_b     = (const float*)d_in[2];
    const float* out_w     = (const float*)d_in[3];
    const float* out_b     = (const float*)d_in[4];
    const float* dpb_w_in  = (const float*)d_in[5];
    const float* dpb_b_in  = (const float*)d_in[6];
    const float* dpb_w_hid = (const float*)d_in[7];
    const float* dpb_b_hid = (const float*)d_in[8];
    const float* dpb_ln_g  = (const float*)d_in[9];
    const float* dpb_ln_b  = (const float*)d_in[10];
    const float* dpb_w_out = (const float*)d_in[11];
    const float* dpb_b_out = (const float*)d_in[12];
    float* out = (float*)d_out;

    // single-buffered attention smem: 2*64*132 + 2*64*68 + 192 floats = ~103 KB
    const int attn_smem =
        (2 * 64 * QS + 2 * 64 * KS + 192) * (int)sizeof(float);
    cudaFuncSetAttribute(attn_kernel, cudaFuncAttributeMaxDynamicSharedMemorySize,
                         attn_smem);

    dpb_kernel<<<256, 192>>>(dpb_w_in, dpb_b_in, dpb_w_hid, dpb_b_hid,
                             dpb_ln_g, dpb_ln_b, dpb_w_out, dpb_b_out);
    transpose_k<<<dim3(128, 24), dim3(32, 8)>>>(x, 0);
    big_gemm<<<dim3(18, 32), 256>>>(qkv_w, 2304, 0, qkv_b, nullptr);
    attn_kernel<<<dim3(16, 24), 256, attn_smem>>>();
    transpose_k<<<dim3(128, 24), dim3(32, 8)>>>(nullptr, 1);
    big_gemm<<<dim3(6, 32), 256>>>(out_w, 768, 1, out_b, out);
}